// round 3
// baseline (speedup 1.0000x reference)
#include <cuda_runtime.h>

// ---------------------------------------------------------------------------
// Output = [B=128, T=512, 66]; all B rows identical (decoder ignores encoder,
// zero init state, constant first input emb[0]). fc folds into the recurrence:
//   g_{t+1} = Wc @ h_t + b_comb,  Wc = dec_W_ih @ fc_W + dec_W_hh  (264 x 66)
//   g_1     = dec_W_ih @ emb[0] + (dec_b_ih + dec_b_hh)
// Rows permuted: gate g of unit u -> row u*4+g.
// Recurrence thread layout (288 threads):
//   tid < 256 : unit u = tid>>2, chunk q = tid&3. Thread computes partial dots
//               of ALL 4 gates of u over h columns [20q, 20q+20). Width-4 shfl
//               butterfly combines the quad -> every lane has all 4 gate
//               pre-activations; lane q activates gate q; lane 0 updates c,h.
//   warp 8    : units 64,65. lane = 4*rl + q, rl = 4*(u-64)+gate. Each lane
//               computes ONE row over chunk q (1/4 the FMA load -> balances
//               SMSP0 which carries warps 0,4,8).
// ---------------------------------------------------------------------------

#define DEC_H 66
#define G4    264
#define EMBED 128
#define CH    20          // h chunk per q
#define HP    80          // padded h length (4*CH)
#define MAXT  1024
#define NTH   288

__device__ __align__(16) float g_W[NTH * 80];        // per-thread swizzled weights
__device__ float g_bias[G4];                          // permuted rows
__device__ float g_gx0[G4];
__device__ __align__(16) float g_hist[MAXT * DEC_H];  // h trajectory [T,66]

typedef unsigned long long ull;

__device__ __forceinline__ void fma2(ull& acc, ull a, ull b) {
    asm("fma.rn.f32x2 %0, %1, %2, %0;" : "+l"(acc) : "l"(a), "l"(b));
}
__device__ __forceinline__ float2 up2(ull v) {
    float2 r;
    asm("mov.b64 {%0, %1}, %2;" : "=f"(r.x), "=f"(r.y) : "l"(v));
    return r;
}
__device__ __forceinline__ ull pack1(float x) {   // (x, 0.f)
    ull r;
    asm("mov.b64 %0, {%1, %2};" : "=l"(r) : "f"(x), "f"(0.0f));
    return r;
}
__device__ __forceinline__ float fast_sigmoid(float x) {
    float e;
    asm("ex2.approx.f32 %0, %1;" : "=f"(e) : "f"(-1.4426950408889634f * x));
    float r;
    asm("rcp.approx.f32 %0, %1;" : "=f"(r) : "f"(1.0f + e));
    return r;                                    // +inf->1, -inf->0 : safe
}
__device__ __forceinline__ float fast_tanh(float x) {
    // tanh(x) = 1 - 2/(e^{2x}+1); e=inf -> 1, e=0 -> -1 : no clamp needed
    float e;
    asm("ex2.approx.f32 %0, %1;" : "=f"(e) : "f"(2.885390081777927f * x));
    float r;
    asm("rcp.approx.f32 %0, %1;" : "=f"(r) : "f"(e + 1.0f));
    return fmaf(-2.0f, r, 1.0f);
}

// ---------------------------------------------------------------------------
// Destination float index in g_W for (permuted row r, column dd).
// Main threads: ull k = p*4+g (p = pair index 0..9). Warp8: ull k = p.
// ---------------------------------------------------------------------------
__device__ __forceinline__ int w_fidx(int r, int dd) {
    int qd = dd / CH;
    int p  = (dd % CH) >> 1;
    int tid, kbase;
    if (r < 256) { tid = (r & ~3) + qd; kbase = ((p << 2) + (r & 3)) << 1; }
    else         { tid = 256 + ((r - 256) << 2) + qd; kbase = p << 1; }
    return tid * 80 + kbase + (dd & 1);
}

// ---------------------------------------------------------------------------
// Kernel 1: fold fc into recurrent matrix; write swizzled layout + bias/gx0.
// grid = 264 (original rows j = gate*66+unit), block = 68.
// ---------------------------------------------------------------------------
__global__ void precompute_kernel(const float* __restrict__ Wih,
                                  const float* __restrict__ Whh,
                                  const float* __restrict__ bih,
                                  const float* __restrict__ bhh,
                                  const float* __restrict__ fcW,
                                  const float* __restrict__ fcb,
                                  const float* __restrict__ emb) {
    __shared__ float wrow[EMBED];
    const int j    = blockIdx.x;
    const int gate = j / DEC_H;
    const int unit = j % DEC_H;
    const int r    = unit * 4 + gate;     // permuted row
    const int d    = threadIdx.x;         // 0..67

    for (int e = d; e < EMBED; e += 68) wrow[e] = Wih[j * EMBED + e];
    __syncthreads();

    if (d < DEC_H) {
        float s0 = 0.f, s1 = 0.f, s2 = 0.f, s3 = 0.f;
        float s4 = 0.f, s5 = 0.f, s6 = 0.f, s7 = 0.f;
#pragma unroll
        for (int e = 0; e < EMBED; e += 8) {
            s0 = fmaf(wrow[e + 0], fcW[(e + 0) * DEC_H + d], s0);
            s1 = fmaf(wrow[e + 1], fcW[(e + 1) * DEC_H + d], s1);
            s2 = fmaf(wrow[e + 2], fcW[(e + 2) * DEC_H + d], s2);
            s3 = fmaf(wrow[e + 3], fcW[(e + 3) * DEC_H + d], s3);
            s4 = fmaf(wrow[e + 4], fcW[(e + 4) * DEC_H + d], s4);
            s5 = fmaf(wrow[e + 5], fcW[(e + 5) * DEC_H + d], s5);
            s6 = fmaf(wrow[e + 6], fcW[(e + 6) * DEC_H + d], s6);
            s7 = fmaf(wrow[e + 7], fcW[(e + 7) * DEC_H + d], s7);
        }
        float v = (((s0 + s1) + (s2 + s3)) + ((s4 + s5) + (s6 + s7)))
                + Whh[j * DEC_H + d];
        g_W[w_fidx(r, d)] = v;
    } else {
        // d==66: bias (fc_b path) + zero pads 66..72
        // d==67: gx0  (emb[0] path) + zero pads 73..79
        const float* vec = (d == DEC_H) ? fcb : emb;   // emb row 0
        float s0 = 0.f, s1 = 0.f, s2 = 0.f, s3 = 0.f;
        float s4 = 0.f, s5 = 0.f, s6 = 0.f, s7 = 0.f;
#pragma unroll
        for (int e = 0; e < EMBED; e += 8) {
            s0 = fmaf(wrow[e + 0], vec[e + 0], s0);
            s1 = fmaf(wrow[e + 1], vec[e + 1], s1);
            s2 = fmaf(wrow[e + 2], vec[e + 2], s2);
            s3 = fmaf(wrow[e + 3], vec[e + 3], s3);
            s4 = fmaf(wrow[e + 4], vec[e + 4], s4);
            s5 = fmaf(wrow[e + 5], vec[e + 5], s5);
            s6 = fmaf(wrow[e + 6], vec[e + 6], s6);
            s7 = fmaf(wrow[e + 7], vec[e + 7], s7);
        }
        float sum = ((s0 + s1) + (s2 + s3)) + ((s4 + s5) + (s6 + s7));
        float bb  = bih[j] + bhh[j];
        if (d == DEC_H) g_bias[r] = sum + bb;
        else            g_gx0[r]  = sum + bb;
        int start = (d == DEC_H) ? DEC_H : 73;
        int end   = (d == DEC_H) ? 73    : HP;
        for (int dd = start; dd < end; dd++) g_W[w_fidx(r, dd)] = 0.0f;
    }
}

// ---------------------------------------------------------------------------
// Kernel 2: sequential recurrence. 1 CTA, 288 threads, 1 barrier/step.
// ---------------------------------------------------------------------------
__global__ __launch_bounds__(NTH, 1) void recur_kernel(int T) {
    __shared__ __align__(16) float hsm[2][HP];
    const int  tid  = threadIdx.x;
    const int  lane = tid & 31;
    const bool w8   = (tid >= 256);
    const int  q    = tid & 3;

    // weights resident in registers
    ull w[40];
    const ull* wsrc = reinterpret_cast<const ull*>(g_W) + tid * 40;
#pragma unroll
    for (int k = 0; k < 40; k++) w[k] = wsrc[k];

    const int myrow = w8 ? (256 + (lane >> 2)) : tid;
    const float bias = g_bias[myrow];
    const float gx0  = g_gx0[myrow];

    // bias folded into accumulator init: lane q seeds acc[q]
    ull bini[4], bmain[4];
#pragma unroll
    for (int g = 0; g < 4; g++) {
        bini[g]  = (g == q) ? pack1(gx0)  : 0ull;
        bmain[g] = (g == q) ? pack1(bias) : 0ull;
    }

    if (tid < 2 * HP) reinterpret_cast<float*>(hsm)[tid] = 0.0f;
    float cst = 0.0f;
    const int myg = w8 ? ((lane >> 2) & 3) : q;      // gate type for activation
    const int u   = w8 ? (64 + (lane >> 4)) : (tid >> 2);
    __syncthreads();

    for (int t = 0; t < T; t++) {
        const ulonglong2* h2 =
            reinterpret_cast<const ulonglong2*>(&hsm[t & 1][q * CH]);
        float red;
        if (!w8) {
            ull a0 = bini[0], a1 = bini[1], a2 = bini[2], a3 = bini[3];
#pragma unroll
            for (int pp = 0; pp < 5; pp++) {
                ulonglong2 hv = h2[pp];              // broadcast LDS.128
                fma2(a0, w[(2 * pp) * 4 + 0], hv.x);
                fma2(a1, w[(2 * pp) * 4 + 1], hv.x);
                fma2(a2, w[(2 * pp) * 4 + 2], hv.x);
                fma2(a3, w[(2 * pp) * 4 + 3], hv.x);
                fma2(a0, w[(2 * pp + 1) * 4 + 0], hv.y);
                fma2(a1, w[(2 * pp + 1) * 4 + 1], hv.y);
                fma2(a2, w[(2 * pp + 1) * 4 + 2], hv.y);
                fma2(a3, w[(2 * pp + 1) * 4 + 3], hv.y);
            }
            float2 f0 = up2(a0), f1 = up2(a1), f2 = up2(a2), f3 = up2(a3);
            float s0 = f0.x + f0.y, s1 = f1.x + f1.y;
            float s2 = f2.x + f2.y, s3 = f3.x + f3.y;
            // width-4 butterfly: every lane ends with all 4 gate totals
            s0 += __shfl_xor_sync(~0u, s0, 1);
            s1 += __shfl_xor_sync(~0u, s1, 1);
            s2 += __shfl_xor_sync(~0u, s2, 1);
            s3 += __shfl_xor_sync(~0u, s3, 1);
            s0 += __shfl_xor_sync(~0u, s0, 2);
            s1 += __shfl_xor_sync(~0u, s1, 2);
            s2 += __shfl_xor_sync(~0u, s2, 2);
            s3 += __shfl_xor_sync(~0u, s3, 2);
            red = (q == 0) ? s0 : (q == 1) ? s1 : (q == 2) ? s2 : s3;
        } else {
            ull a = bini[0];                          // nonzero only at q==0
#pragma unroll
            for (int pp = 0; pp < 5; pp++) {
                ulonglong2 hv = h2[pp];
                fma2(a, w[2 * pp], hv.x);
                fma2(a, w[2 * pp + 1], hv.y);
            }
            float2 f = up2(a);
            float s = f.x + f.y;
            s += __shfl_xor_sync(~0u, s, 1);
            s += __shfl_xor_sync(~0u, s, 2);
            red = s;
        }

        float a_act = (myg == 2) ? fast_tanh(red) : fast_sigmoid(red);

        float fv, gv, ov;
        bool leader;
        if (!w8) {
            fv = __shfl_down_sync(~0u, a_act, 1);
            gv = __shfl_down_sync(~0u, a_act, 2);
            ov = __shfl_down_sync(~0u, a_act, 3);
            leader = (q == 0);
        } else {
            fv = __shfl_down_sync(~0u, a_act, 4);
            gv = __shfl_down_sync(~0u, a_act, 8);
            ov = __shfl_down_sync(~0u, a_act, 12);
            leader = ((lane & 15) == 0);
        }

        if (leader) {
            cst = fmaf(fv, cst, a_act * gv);          // a_act = i at leaders
            float h = ov * fast_tanh(cst);
            hsm[(t + 1) & 1][u] = h;                  // ping-pong write
            g_hist[t * DEC_H + u] = h;
        }
        if (t == 0) {
            bini[0] = bmain[0]; bini[1] = bmain[1];
            bini[2] = bmain[2]; bini[3] = bmain[3];
        }
        __syncthreads();
    }
}

// ---------------------------------------------------------------------------
// Kernel 3: broadcast [T*66] trajectory to all B rows (float4).
// ---------------------------------------------------------------------------
__global__ void bcast_kernel(float* __restrict__ out, int rowlen4) {
    int i = blockIdx.x * blockDim.x + threadIdx.x;
    int b = blockIdx.y;
    if (i < rowlen4) {
        reinterpret_cast<float4*>(out)[(size_t)b * rowlen4 + i] =
            reinterpret_cast<const float4*>(g_hist)[i];
    }
}

// ---------------------------------------------------------------------------
// Inputs: 0:x 1:c 2:emb 3..6:enc_* 7:dec_W_ih 8:dec_W_hh 9:dec_b_ih
// 10:dec_b_hh 11:fc_W 12:fc_b. Encoder is dead code w.r.t. the output.
// ---------------------------------------------------------------------------
extern "C" void kernel_launch(void* const* d_in, const int* in_sizes, int n_in,
                              void* d_out, int out_size) {
    const float* emb = (const float*)d_in[2];
    const float* Wih = (const float*)d_in[7];
    const float* Whh = (const float*)d_in[8];
    const float* bih = (const float*)d_in[9];
    const float* bhh = (const float*)d_in[10];
    const float* fcW = (const float*)d_in[11];
    const float* fcb = (const float*)d_in[12];

    const int B = 128;
    int T = out_size / (B * DEC_H);
    if (T > MAXT) T = MAXT;

    precompute_kernel<<<G4, 68>>>(Wih, Whh, bih, bhh, fcW, fcb, emb);
    recur_kernel<<<1, NTH>>>(T);

    int rowlen4 = (T * DEC_H) / 4;
    dim3 grid((rowlen4 + 255) / 256, B);
    bcast_kernel<<<grid, 256>>>((float*)d_out, rowlen4);
}

// round 4
// speedup vs baseline: 1.0018x; 1.0018x over previous
#include <cuda_runtime.h>

// ---------------------------------------------------------------------------
// Output = [B=128, T=512, 66]; all B rows identical (decoder ignores encoder,
// zero init state, constant first input emb[0]). fc folds into the recurrence:
//   g_{t+1} = Wc @ h_t + b_comb,  Wc = dec_W_ih @ fc_W + dec_W_hh  (264 x 66)
//   g_1     = dec_W_ih @ emb[0] + (dec_b_ih + dec_b_hh)
// Rows permuted: gate g of unit u -> row u*4+g.
// Recurrence thread layout (288 threads):
//   tid < 256 : unit u = tid>>2, chunk q = tid&3. Thread computes partial dots
//               of ALL 4 gates of u over h columns [20q, 20q+20). Width-4 shfl
//               butterfly combines the quad -> every lane has all 4 gate
//               pre-activations; lane q activates gate q; lane 0 updates c,h.
//   warp 8    : units 64,65. lane = 4*rl + q, rl = 4*(u-64)+gate. Each lane
//               computes ONE row over chunk q (1/4 the FMA load -> balances
//               SMSP0 which carries warps 0,4,8).
// ---------------------------------------------------------------------------

#define DEC_H 66
#define G4    264
#define EMBED 128
#define CH    20          // h chunk per q
#define HP    80          // padded h length (4*CH)
#define MAXT  1024
#define NTH   288

__device__ __align__(16) float g_W[NTH * 80];        // per-thread swizzled weights
__device__ float g_bias[G4];                          // permuted rows
__device__ float g_gx0[G4];
__device__ __align__(16) float g_hist[MAXT * DEC_H];  // h trajectory [T,66]

typedef unsigned long long ull;

__device__ __forceinline__ void fma2(ull& acc, ull a, ull b) {
    asm("fma.rn.f32x2 %0, %1, %2, %0;" : "+l"(acc) : "l"(a), "l"(b));
}
__device__ __forceinline__ float2 up2(ull v) {
    float2 r;
    asm("mov.b64 {%0, %1}, %2;" : "=f"(r.x), "=f"(r.y) : "l"(v));
    return r;
}
__device__ __forceinline__ ull pack1(float x) {   // (x, 0.f)
    ull r;
    asm("mov.b64 %0, {%1, %2};" : "=l"(r) : "f"(x), "f"(0.0f));
    return r;
}
__device__ __forceinline__ float fast_sigmoid(float x) {
    float e;
    asm("ex2.approx.f32 %0, %1;" : "=f"(e) : "f"(-1.4426950408889634f * x));
    float r;
    asm("rcp.approx.f32 %0, %1;" : "=f"(r) : "f"(1.0f + e));
    return r;                                    // +inf->1, -inf->0 : safe
}
__device__ __forceinline__ float fast_tanh(float x) {
    // tanh(x) = 1 - 2/(e^{2x}+1); e=inf -> 1, e=0 -> -1 : no clamp needed
    float e;
    asm("ex2.approx.f32 %0, %1;" : "=f"(e) : "f"(2.885390081777927f * x));
    float r;
    asm("rcp.approx.f32 %0, %1;" : "=f"(r) : "f"(e + 1.0f));
    return fmaf(-2.0f, r, 1.0f);
}

// ---------------------------------------------------------------------------
// Destination float index in g_W for (permuted row r, column dd).
// Main threads: ull k = p*4+g (p = pair index 0..9). Warp8: ull k = p.
// ---------------------------------------------------------------------------
__device__ __forceinline__ int w_fidx(int r, int dd) {
    int qd = dd / CH;
    int p  = (dd % CH) >> 1;
    int tid, kbase;
    if (r < 256) { tid = (r & ~3) + qd; kbase = ((p << 2) + (r & 3)) << 1; }
    else         { tid = 256 + ((r - 256) << 2) + qd; kbase = p << 1; }
    return tid * 80 + kbase + (dd & 1);
}

// ---------------------------------------------------------------------------
// Kernel 1: fold fc into recurrent matrix; write swizzled layout + bias/gx0.
// grid = 264 (original rows j = gate*66+unit), block = 68.
// ---------------------------------------------------------------------------
__global__ void precompute_kernel(const float* __restrict__ Wih,
                                  const float* __restrict__ Whh,
                                  const float* __restrict__ bih,
                                  const float* __restrict__ bhh,
                                  const float* __restrict__ fcW,
                                  const float* __restrict__ fcb,
                                  const float* __restrict__ emb) {
    __shared__ float wrow[EMBED];
    const int j    = blockIdx.x;
    const int gate = j / DEC_H;
    const int unit = j % DEC_H;
    const int r    = unit * 4 + gate;     // permuted row
    const int d    = threadIdx.x;         // 0..67

    for (int e = d; e < EMBED; e += 68) wrow[e] = Wih[j * EMBED + e];
    __syncthreads();

    if (d < DEC_H) {
        float s0 = 0.f, s1 = 0.f, s2 = 0.f, s3 = 0.f;
        float s4 = 0.f, s5 = 0.f, s6 = 0.f, s7 = 0.f;
#pragma unroll
        for (int e = 0; e < EMBED; e += 8) {
            s0 = fmaf(wrow[e + 0], fcW[(e + 0) * DEC_H + d], s0);
            s1 = fmaf(wrow[e + 1], fcW[(e + 1) * DEC_H + d], s1);
            s2 = fmaf(wrow[e + 2], fcW[(e + 2) * DEC_H + d], s2);
            s3 = fmaf(wrow[e + 3], fcW[(e + 3) * DEC_H + d], s3);
            s4 = fmaf(wrow[e + 4], fcW[(e + 4) * DEC_H + d], s4);
            s5 = fmaf(wrow[e + 5], fcW[(e + 5) * DEC_H + d], s5);
            s6 = fmaf(wrow[e + 6], fcW[(e + 6) * DEC_H + d], s6);
            s7 = fmaf(wrow[e + 7], fcW[(e + 7) * DEC_H + d], s7);
        }
        float v = (((s0 + s1) + (s2 + s3)) + ((s4 + s5) + (s6 + s7)))
                + Whh[j * DEC_H + d];
        g_W[w_fidx(r, d)] = v;
    } else {
        // d==66: bias (fc_b path) + zero pads 66..72
        // d==67: gx0  (emb[0] path) + zero pads 73..79
        const float* vec = (d == DEC_H) ? fcb : emb;   // emb row 0
        float s0 = 0.f, s1 = 0.f, s2 = 0.f, s3 = 0.f;
        float s4 = 0.f, s5 = 0.f, s6 = 0.f, s7 = 0.f;
#pragma unroll
        for (int e = 0; e < EMBED; e += 8) {
            s0 = fmaf(wrow[e + 0], vec[e + 0], s0);
            s1 = fmaf(wrow[e + 1], vec[e + 1], s1);
            s2 = fmaf(wrow[e + 2], vec[e + 2], s2);
            s3 = fmaf(wrow[e + 3], vec[e + 3], s3);
            s4 = fmaf(wrow[e + 4], vec[e + 4], s4);
            s5 = fmaf(wrow[e + 5], vec[e + 5], s5);
            s6 = fmaf(wrow[e + 6], vec[e + 6], s6);
            s7 = fmaf(wrow[e + 7], vec[e + 7], s7);
        }
        float sum = ((s0 + s1) + (s2 + s3)) + ((s4 + s5) + (s6 + s7));
        float bb  = bih[j] + bhh[j];
        if (d == DEC_H) g_bias[r] = sum + bb;
        else            g_gx0[r]  = sum + bb;
        int start = (d == DEC_H) ? DEC_H : 73;
        int end   = (d == DEC_H) ? 73    : HP;
        for (int dd = start; dd < end; dd++) g_W[w_fidx(r, dd)] = 0.0f;
    }
}

// ---------------------------------------------------------------------------
// Kernel 2: sequential recurrence. 1 CTA, 288 threads, 1 barrier/step.
// ---------------------------------------------------------------------------
__global__ __launch_bounds__(NTH, 1) void recur_kernel(int T) {
    __shared__ __align__(16) float hsm[2][HP];
    const int  tid  = threadIdx.x;
    const int  lane = tid & 31;
    const bool w8   = (tid >= 256);
    const int  q    = tid & 3;

    // weights resident in registers
    ull w[40];
    const ull* wsrc = reinterpret_cast<const ull*>(g_W) + tid * 40;
#pragma unroll
    for (int k = 0; k < 40; k++) w[k] = wsrc[k];

    const int myrow = w8 ? (256 + (lane >> 2)) : tid;
    const float bias = g_bias[myrow];
    const float gx0  = g_gx0[myrow];

    // bias folded into accumulator init: lane q seeds acc[q]
    ull bini[4], bmain[4];
#pragma unroll
    for (int g = 0; g < 4; g++) {
        bini[g]  = (g == q) ? pack1(gx0)  : 0ull;
        bmain[g] = (g == q) ? pack1(bias) : 0ull;
    }

    if (tid < 2 * HP) reinterpret_cast<float*>(hsm)[tid] = 0.0f;
    float cst = 0.0f;
    const int myg = w8 ? ((lane >> 2) & 3) : q;      // gate type for activation
    const int u   = w8 ? (64 + (lane >> 4)) : (tid >> 2);
    __syncthreads();

    for (int t = 0; t < T; t++) {
        const ulonglong2* h2 =
            reinterpret_cast<const ulonglong2*>(&hsm[t & 1][q * CH]);
        float red;
        if (!w8) {
            ull a0 = bini[0], a1 = bini[1], a2 = bini[2], a3 = bini[3];
#pragma unroll
            for (int pp = 0; pp < 5; pp++) {
                ulonglong2 hv = h2[pp];              // broadcast LDS.128
                fma2(a0, w[(2 * pp) * 4 + 0], hv.x);
                fma2(a1, w[(2 * pp) * 4 + 1], hv.x);
                fma2(a2, w[(2 * pp) * 4 + 2], hv.x);
                fma2(a3, w[(2 * pp) * 4 + 3], hv.x);
                fma2(a0, w[(2 * pp + 1) * 4 + 0], hv.y);
                fma2(a1, w[(2 * pp + 1) * 4 + 1], hv.y);
                fma2(a2, w[(2 * pp + 1) * 4 + 2], hv.y);
                fma2(a3, w[(2 * pp + 1) * 4 + 3], hv.y);
            }
            float2 f0 = up2(a0), f1 = up2(a1), f2 = up2(a2), f3 = up2(a3);
            float s0 = f0.x + f0.y, s1 = f1.x + f1.y;
            float s2 = f2.x + f2.y, s3 = f3.x + f3.y;
            // width-4 butterfly: every lane ends with all 4 gate totals
            s0 += __shfl_xor_sync(~0u, s0, 1);
            s1 += __shfl_xor_sync(~0u, s1, 1);
            s2 += __shfl_xor_sync(~0u, s2, 1);
            s3 += __shfl_xor_sync(~0u, s3, 1);
            s0 += __shfl_xor_sync(~0u, s0, 2);
            s1 += __shfl_xor_sync(~0u, s1, 2);
            s2 += __shfl_xor_sync(~0u, s2, 2);
            s3 += __shfl_xor_sync(~0u, s3, 2);
            red = (q == 0) ? s0 : (q == 1) ? s1 : (q == 2) ? s2 : s3;
        } else {
            ull a = bini[0];                          // nonzero only at q==0
#pragma unroll
            for (int pp = 0; pp < 5; pp++) {
                ulonglong2 hv = h2[pp];
                fma2(a, w[2 * pp], hv.x);
                fma2(a, w[2 * pp + 1], hv.y);
            }
            float2 f = up2(a);
            float s = f.x + f.y;
            s += __shfl_xor_sync(~0u, s, 1);
            s += __shfl_xor_sync(~0u, s, 2);
            red = s;
        }

        float a_act = (myg == 2) ? fast_tanh(red) : fast_sigmoid(red);

        float fv, gv, ov;
        bool leader;
        if (!w8) {
            fv = __shfl_down_sync(~0u, a_act, 1);
            gv = __shfl_down_sync(~0u, a_act, 2);
            ov = __shfl_down_sync(~0u, a_act, 3);
            leader = (q == 0);
        } else {
            fv = __shfl_down_sync(~0u, a_act, 4);
            gv = __shfl_down_sync(~0u, a_act, 8);
            ov = __shfl_down_sync(~0u, a_act, 12);
            leader = ((lane & 15) == 0);
        }

        if (leader) {
            cst = fmaf(fv, cst, a_act * gv);          // a_act = i at leaders
            float h = ov * fast_tanh(cst);
            hsm[(t + 1) & 1][u] = h;                  // ping-pong write
            g_hist[t * DEC_H + u] = h;
        }
        if (t == 0) {
            bini[0] = bmain[0]; bini[1] = bmain[1];
            bini[2] = bmain[2]; bini[3] = bmain[3];
        }
        __syncthreads();
    }
}

// ---------------------------------------------------------------------------
// Kernel 3: broadcast [T*66] trajectory to all B rows (float4).
// ---------------------------------------------------------------------------
__global__ void bcast_kernel(float* __restrict__ out, int rowlen4) {
    int i = blockIdx.x * blockDim.x + threadIdx.x;
    int b = blockIdx.y;
    if (i < rowlen4) {
        reinterpret_cast<float4*>(out)[(size_t)b * rowlen4 + i] =
            reinterpret_cast<const float4*>(g_hist)[i];
    }
}

// ---------------------------------------------------------------------------
// Inputs: 0:x 1:c 2:emb 3..6:enc_* 7:dec_W_ih 8:dec_W_hh 9:dec_b_ih
// 10:dec_b_hh 11:fc_W 12:fc_b. Encoder is dead code w.r.t. the output.
// ---------------------------------------------------------------------------
extern "C" void kernel_launch(void* const* d_in, const int* in_sizes, int n_in,
                              void* d_out, int out_size) {
    const float* emb = (const float*)d_in[2];
    const float* Wih = (const float*)d_in[7];
    const float* Whh = (const float*)d_in[8];
    const float* bih = (const float*)d_in[9];
    const float* bhh = (const float*)d_in[10];
    const float* fcW = (const float*)d_in[11];
    const float* fcb = (const float*)d_in[12];

    const int B = 128;
    int T = out_size / (B * DEC_H);
    if (T > MAXT) T = MAXT;

    precompute_kernel<<<G4, 68>>>(Wih, Whh, bih, bhh, fcW, fcb, emb);
    recur_kernel<<<1, NTH>>>(T);

    int rowlen4 = (T * DEC_H) / 4;
    dim3 grid((rowlen4 + 255) / 256, B);
    bcast_kernel<<<grid, 256>>>((float*)d_out, rowlen4);
}